// round 14
// baseline (speedup 1.0000x reference)
#include <cuda_runtime.h>
#include <cuda_bf16.h>
#include <cstdint>

#define Bv 128
#define Sv 1024
#define Fv 512
#define Hv 128
#define G3 (3*Hv)
#define STR 40                  // smem row stride in bf16 elems (32 data + 8 pad)
#define ARR (128*STR)           // elems per smem array (5120)
#define BUFE (4*ARR)            // elems per buffer (A_hi, A_lo, W_hi, W_lo)
#define SMEM_DYN (2*BUFE*2)     // bytes: double-buffered (81920)

typedef unsigned long long ull;

// ---------------- scratch (static device arrays; no allocation) ----------------
__device__ float    g_xg[(size_t)Bv * Sv * G3];     // xg0 / xg1
__device__ uint16_t g_Ahi[(size_t)Bv * Sv * Hv];    // bf16 hi of proj, then h1
__device__ uint16_t g_Alo[(size_t)Bv * Sv * Hv];    // bf16 lo
__device__ uint16_t g_Wphi[Hv * Fv], g_Wplo[Hv * Fv];
__device__ uint16_t g_W0hi[G3 * Hv], g_W0lo[G3 * Hv];
__device__ uint16_t g_W1hi[G3 * Hv], g_W1lo[G3 * Hv];
__device__ int      g_len[Bv];
__device__ int      g_rank[Bv];

// ---------------- f32x2 helpers ----------------
static __device__ __forceinline__ ull pk2(float x, float y) {
    ull r;
    asm("mov.b64 %0, {%1, %2};" : "=l"(r) : "f"(x), "f"(y));
    return r;
}
static __device__ __forceinline__ void fma2p(ull &d, ull a, ull b) {
    asm("fma.rn.f32x2 %0, %1, %2, %0;" : "+l"(d) : "l"(a), "l"(b));
}
static __device__ __forceinline__ float2 upk(ull v) {
    float2 f;
    asm("mov.b64 {%0, %1}, %2;" : "=f"(f.x), "=f"(f.y) : "l"(v));
    return f;
}
static __device__ __forceinline__ float fsig(float x) {
    return __fdividef(1.0f, 1.0f + __expf(-x));
}
static __device__ __forceinline__ float ftanh(float x) {
    float e = __expf(2.0f * x);
    return 1.0f - __fdividef(2.0f, e + 1.0f);
}

// ---------------- mma helpers ----------------
static __device__ __forceinline__ uint32_t smem_u32(const void* p) {
    uint32_t a;
    asm("{ .reg .u64 t; cvta.to.shared.u64 t, %1; cvt.u32.u64 %0, t; }" : "=r"(a) : "l"(p));
    return a;
}
static __device__ __forceinline__ void ldm4(uint32_t r[4], uint32_t a) {
    asm volatile("ldmatrix.sync.aligned.m8n8.x4.shared.b16 {%0,%1,%2,%3}, [%4];"
                 : "=r"(r[0]), "=r"(r[1]), "=r"(r[2]), "=r"(r[3]) : "r"(a));
}
static __device__ __forceinline__ void mma16816(float d[4], const uint32_t a[4], const uint32_t b[2]) {
    asm volatile(
        "mma.sync.aligned.m16n8k16.row.col.f32.bf16.bf16.f32 "
        "{%0,%1,%2,%3}, {%4,%5,%6,%7}, {%8,%9}, {%0,%1,%2,%3};"
        : "+f"(d[0]), "+f"(d[1]), "+f"(d[2]), "+f"(d[3])
        : "r"(a[0]), "r"(a[1]), "r"(a[2]), "r"(a[3]), "r"(b[0]), "r"(b[1]));
}
// convert 8 fp32 -> 4 bf16x2 hi words + 4 lo (residual) words, store as uint4
static __device__ __forceinline__ void cvt_store(uint16_t* dst_hi, uint16_t* dst_lo,
                                                 const float f[8]) {
    uint32_t hw[4], lw[4];
#pragma unroll
    for (int j = 0; j < 4; j++) {
        float e0 = f[2 * j], e1 = f[2 * j + 1];
        uint32_t h;
        asm("cvt.rn.bf16x2.f32 %0, %1, %2;" : "=r"(h) : "f"(e1), "f"(e0)); // lo=e0, hi=e1
        float h0 = __uint_as_float(h << 16);
        float h1 = __uint_as_float(h & 0xffff0000u);
        float l0 = e0 - h0, l1 = e1 - h1;  // exact (Sterbenz)
        uint32_t l;
        asm("cvt.rn.bf16x2.f32 %0, %1, %2;" : "=r"(l) : "f"(l1), "f"(l0));
        hw[j] = h; lw[j] = l;
    }
    *(uint4*)dst_hi = make_uint4(hw[0], hw[1], hw[2], hw[3]);
    *(uint4*)dst_lo = make_uint4(lw[0], lw[1], lw[2], lw[3]);
}

// ---------------- weight pre-conversion: fp32 -> bf16 hi/lo ----------------
__global__ void convw(const float* __restrict__ src,
                      uint16_t* __restrict__ hi, uint16_t* __restrict__ lo, int n) {
    int i = blockIdx.x * blockDim.x + threadIdx.x;
    if (i < n) {
        float v = src[i];
        __nv_bfloat16 h = __float2bfloat16(v);
        hi[i] = *(uint16_t*)&h;
        float l = v - __bfloat162float(h);
        __nv_bfloat16 hl = __float2bfloat16(l);
        lo[i] = *(uint16_t*)&hl;
    }
}

// ---------------- tensor-core GEMM: C[m,n] = A[m,:K].W[n,:K] + bias[n] ----------------
// 512 threads, 128x128 tile, K chunk 32, DOUBLE-BUFFERED dynamic smem.
// W always pre-converted bf16 hi/lo.  A either fp32 (converted in-kernel) or
// pre-converted bf16.  bf16 3-split: D = Ah.Wh + Al.Wh + Ah.Wl.
template <bool A_BF16, bool WRITE_F32, bool WRITE_BF16>
__global__ void __launch_bounds__(512, 1) gemm_mma(
    const float* __restrict__ Af,
    const uint16_t* __restrict__ Ahi, const uint16_t* __restrict__ Alo,
    const uint16_t* __restrict__ Whi, const uint16_t* __restrict__ Wlo,
    const float* __restrict__ bias,
    float* __restrict__ C, uint16_t* __restrict__ Chi, uint16_t* __restrict__ Clo,
    int K, int N)
{
    extern __shared__ __align__(16) uint16_t sdyn[];

    const int tid = threadIdx.x, lane = tid & 31, wid = tid >> 5;
    const int wm = wid & 3, wn = wid >> 2;
    const int m0 = blockIdx.x * 128, n0 = blockIdx.y * 128;

    const int srow = tid >> 2, scg = tid & 3;
    const int selem = srow * STR + scg * 8;        // multiple of 8 -> 16B aligned

    const float*    Ag  = A_BF16 ? nullptr : (Af  + (size_t)(m0 + srow) * K + scg * 8);
    const uint16_t* Agh = A_BF16 ? (Ahi + (size_t)(m0 + srow) * K + scg * 8) : nullptr;
    const uint16_t* Agl = A_BF16 ? (Alo + (size_t)(m0 + srow) * K + scg * 8) : nullptr;
    const uint16_t* Wgh = Whi + (size_t)(n0 + srow) * K + scg * 8;
    const uint16_t* Wgl = Wlo + (size_t)(n0 + srow) * K + scg * 8;

    const uint32_t sbase = smem_u32(sdyn);

    // ldmatrix lane-address components (element offsets)
    const int a_r = lane & 15;
    const int a_c = (lane >> 4) << 3;
    const int b_r = (lane & 7) + ((lane >> 4) << 3);
    const int b_c = ((lane >> 3) & 1) << 3;

    float acc[2][4][4];
#pragma unroll
    for (int i = 0; i < 2; i++)
#pragma unroll
        for (int j = 0; j < 4; j++)
#pragma unroll
            for (int q = 0; q < 4; q++) acc[i][j][q] = 0.0f;

    const int nch = K >> 5;

    float fa[8];
    uint4 rAh, rAl, rWh, rWl;
    if (A_BF16) {
        rAh = *(const uint4*)Agh;
        rAl = *(const uint4*)Agl;
    } else {
        float4 v0 = ((const float4*)Ag)[0], v1 = ((const float4*)Ag)[1];
        fa[0]=v0.x; fa[1]=v0.y; fa[2]=v0.z; fa[3]=v0.w;
        fa[4]=v1.x; fa[5]=v1.y; fa[6]=v1.z; fa[7]=v1.w;
    }
    rWh = *(const uint4*)Wgh;
    rWl = *(const uint4*)Wgl;

    auto stage = [&](int buf) {
        uint16_t* bp = sdyn + buf * BUFE;
        if (A_BF16) {
            *(uint4*)(bp + selem)       = rAh;
            *(uint4*)(bp + ARR + selem) = rAl;
        } else {
            cvt_store(bp + selem, bp + ARR + selem, fa);
        }
        *(uint4*)(bp + 2 * ARR + selem) = rWh;
        *(uint4*)(bp + 3 * ARR + selem) = rWl;
    };

    stage(0);
    __syncthreads();

    for (int c = 0; c < nch; c++) {
        const int cur = c & 1;
        if (c + 1 < nch) {
            const int off = (c + 1) * 32;
            if (A_BF16) {
                rAh = *(const uint4*)(Agh + off);
                rAl = *(const uint4*)(Agl + off);
            } else {
                float4 v0 = ((const float4*)(Ag + off))[0], v1 = ((const float4*)(Ag + off))[1];
                fa[0]=v0.x; fa[1]=v0.y; fa[2]=v0.z; fa[3]=v0.w;
                fa[4]=v1.x; fa[5]=v1.y; fa[6]=v1.z; fa[7]=v1.w;
            }
            rWh = *(const uint4*)(Wgh + off);
            rWl = *(const uint4*)(Wgl + off);
        }

        const uint32_t base = sbase + (uint32_t)cur * (BUFE * 2u);
        const uint32_t uAh = base;
        const uint32_t uAl = base + ARR * 2u;
        const uint32_t uWh = base + 2u * ARR * 2u;
        const uint32_t uWl = base + 3u * ARR * 2u;

#pragma unroll
        for (int kb = 0; kb < 32; kb += 16) {
            uint32_t ah[2][4], al[2][4];
#pragma unroll
            for (int mf = 0; mf < 2; mf++) {
                uint32_t off = ((uint32_t)(wm * 32 + mf * 16 + a_r) * STR + kb + a_c) * 2;
                ldm4(ah[mf], uAh + off);
                ldm4(al[mf], uAl + off);
            }
            uint32_t bh[2][4], bl[2][4];
#pragma unroll
            for (int nf2 = 0; nf2 < 2; nf2++) {
                uint32_t off = ((uint32_t)(wn * 32 + nf2 * 16 + b_r) * STR + kb + b_c) * 2;
                ldm4(bh[nf2], uWh + off);
                ldm4(bl[nf2], uWl + off);
            }
#pragma unroll
            for (int mf = 0; mf < 2; mf++)
#pragma unroll
                for (int nf = 0; nf < 4; nf++) {
                    const uint32_t* bfh = &bh[nf >> 1][(nf & 1) * 2];
                    const uint32_t* bfl = &bl[nf >> 1][(nf & 1) * 2];
                    mma16816(acc[mf][nf], ah[mf], bfh);
                    mma16816(acc[mf][nf], al[mf], bfh);
                    mma16816(acc[mf][nf], ah[mf], bfl);
                }
        }
        if (c + 1 < nch) {
            stage(cur ^ 1);
            __syncthreads();
        }
    }

    // epilogue: warp covers rows [wm*32, +32), cols [wn*32, +32)
    const int erow = wm * 32 + (lane >> 2);
    const int ecol = wn * 32 + 2 * (lane & 3);
#pragma unroll
    for (int mf = 0; mf < 2; mf++) {
#pragma unroll
        for (int nf = 0; nf < 4; nf++) {
            const int r = m0 + erow + mf * 16;
            const int col = n0 + ecol + nf * 8;
            const float b0 = bias[col], b1 = bias[col + 1];
            float c0 = acc[mf][nf][0] + b0, c1 = acc[mf][nf][1] + b1;
            float c2 = acc[mf][nf][2] + b0, c3 = acc[mf][nf][3] + b1;
            if (WRITE_F32) {
                *(float2*)(C + (size_t)r * N + col) = make_float2(c0, c1);
                *(float2*)(C + (size_t)(r + 8) * N + col) = make_float2(c2, c3);
            }
            if (WRITE_BF16) {
                uint32_t H0, L0, H1, L1;
                asm("cvt.rn.bf16x2.f32 %0, %1, %2;" : "=r"(H0) : "f"(c1), "f"(c0));
                float h0 = __uint_as_float(H0 << 16);
                float h1 = __uint_as_float(H0 & 0xffff0000u);
                asm("cvt.rn.bf16x2.f32 %0, %1, %2;" : "=r"(L0) : "f"(c1 - h1), "f"(c0 - h0));
                asm("cvt.rn.bf16x2.f32 %0, %1, %2;" : "=r"(H1) : "f"(c3), "f"(c2));
                float h2 = __uint_as_float(H1 << 16);
                float h3 = __uint_as_float(H1 & 0xffff0000u);
                asm("cvt.rn.bf16x2.f32 %0, %1, %2;" : "=r"(L1) : "f"(c3 - h3), "f"(c2 - h2));
                *(uint32_t*)(Chi + (size_t)r * N + col) = H0;
                *(uint32_t*)(Clo + (size_t)r * N + col) = L0;
                *(uint32_t*)(Chi + (size_t)(r + 8) * N + col) = H1;
                *(uint32_t*)(Clo + (size_t)(r + 8) * N + col) = L1;
            }
        }
    }
}

// ---------------- lengths: count nonzero rows per batch ----------------
__global__ void lengths_kernel(const float* __restrict__ x, int* __restrict__ len) {
    const int b = blockIdx.x;
    const int warp = threadIdx.x >> 5, lane = threadIdx.x & 31;
    __shared__ int cnt;
    if (threadIdx.x == 0) cnt = 0;
    __syncthreads();
    int local = 0;
    for (int s = warp; s < Sv; s += 8) {
        const float2* row = (const float2*)(x + ((size_t)b * Sv + s) * Fv);
        float2 v = row[lane];
        bool nz = (v.x != 0.0f) || (v.y != 0.0f);
        if (__any_sync(0xffffffffu, nz)) local++;
    }
    if (lane == 0) atomicAdd(&cnt, local);
    __syncthreads();
    if (threadIdx.x == 0) len[b] = cnt;
}

// ---------------- stable-descending rank ----------------
__global__ void rank_kernel(const int* __restrict__ len, int* __restrict__ rank) {
    const int b = threadIdx.x;
    const int L = len[b];
    int r = 0;
    for (int j = 0; j < Bv; j++) {
        int Lj = len[j];
        r += (Lj > L) || (Lj == L && j < b);
    }
    rank[b] = r;
}

// ---------------- GRU recurrence: 768 threads, lane-pair row split ----------------
// Lane pair (even,odd) shares gate-row  row = warp*16 + lane/2;  each thread
// dots HALF of h (w = 32 f32x2 regs), combined by shfl_xor(1).  24 warps
// (6/SMSP) hide barrier/LDS/MUFU latency that 12 warps could not.
// Sigmoids hoisted into the dot phase (even lanes); combine on threads 0-127.
template <bool LAST>
__global__ void __launch_bounds__(768, 1) gru_layer_kernel(
    const float* __restrict__ xg,   // [Bv,Sv,3H]
    const float* __restrict__ Whh,  // [3H,H]
    const float* __restrict__ bhh,  // [3H]
    const int* __restrict__ len,
    uint16_t* __restrict__ h_hi,    // [Bv,Sv,H] when !LAST
    uint16_t* __restrict__ h_lo,
    float* __restrict__ out,        // [Bv,H] when LAST (sorted order)
    const int* __restrict__ rank)
{
    const int b = blockIdx.x;
    const int t = threadIdx.x;
    const int lane = t & 31;
    const int row  = (t >> 5) * 16 + (lane >> 1);   // 0..383
    const int half = lane & 1;
    const int gate = row >> 7;                      // 0=r 1=z 2=n
    const int j = row & (Hv - 1);

    __shared__ __align__(16) float h_sh[Hv];
    __shared__ float r_sh[Hv];
    __shared__ float omz_sh[Hv];   // 1 - z
    __shared__ float zh_sh[Hv];    // z * h_prev
    __shared__ float hn_sh[Hv];
    __shared__ float xn_sh[Hv];

    // half-row weights: Whh[row, half*64 .. half*64+64) -> 32 f32x2
    ull w[32];
    {
        const float4* wp = (const float4*)(Whh + (size_t)row * Hv + half * 64);
#pragma unroll
        for (int i = 0; i < 16; i++) {
            float4 v = wp[i];
            w[2 * i]     = pk2(v.x, v.y);
            w[2 * i + 1] = pk2(v.z, v.w);
        }
    }
    const float bh = bhh[row];
    const int L = len[b];
    const float* xb = xg + (size_t)b * Sv * G3 + row;

    if (t < Hv) h_sh[t] = 0.0f;
    float x0 = (L > 0) ? xb[0] : 0.0f;
    __syncthreads();

    float oacc = 0.0f;

    for (int s = 0; s < L; s++) {
        float xN = (s + 1 < L) ? xb[(size_t)(s + 1) * G3] : 0.0f;

        // half-dot: 32 f32x2 FMAs over h[half*64 .. +64)
        ull a0 = (half == 0) ? pk2((gate == 2) ? bh : (bh + x0), 0.0f) : 0ull;
        ull a1 = 0ull;
        const ulonglong2* hp = ((const ulonglong2*)h_sh) + half * 16;
#pragma unroll
        for (int i = 0; i < 16; i++) {
            ulonglong2 hv = hp[i];
            fma2p(a0, w[2 * i],     hv.x);
            fma2p(a1, w[2 * i + 1], hv.y);
        }
        float2 f0 = upk(a0), f1 = upk(a1);
        float v = (f0.x + f1.x) + (f0.y + f1.y);
        v += __shfl_xor_sync(0xffffffffu, v, 1);

        if (half == 0) {
            if (gate == 0) {
                r_sh[j] = fsig(v);
            } else if (gate == 1) {
                float z = fsig(v);
                omz_sh[j] = 1.0f - z;
                zh_sh[j] = z * h_sh[j];
            } else {
                hn_sh[j] = v;
                xn_sh[j] = x0;
            }
        }
        __syncthreads();

        if (t < Hv) {
            float n = ftanh(fmaf(r_sh[t], hn_sh[t], xn_sh[t]));
            float hnew = fmaf(n, omz_sh[t], zh_sh[t]);
            h_sh[t] = hnew;
            if (!LAST) {
                size_t idx = ((size_t)b * Sv + s) * Hv + t;
                __nv_bfloat16 hh = __float2bfloat16(hnew);
                h_hi[idx] = *(uint16_t*)&hh;
                float rem = hnew - __bfloat162float(hh);
                __nv_bfloat16 hl = __float2bfloat16(rem);
                h_lo[idx] = *(uint16_t*)&hl;
            } else {
                oacc += hnew;
            }
        }
        __syncthreads();
        x0 = xN;
    }

    if (LAST && t < Hv) {
        out[(size_t)rank[b] * Hv + t] = oacc * (1.0f / (float)Sv);
    }
}

// ---------------- launch ----------------
extern "C" void kernel_launch(void* const* d_in, const int* in_sizes, int n_in,
                              void* d_out, int out_size) {
    (void)in_sizes; (void)n_in; (void)out_size;
    const float* x    = (const float*)d_in[0];
    const float* Wp   = (const float*)d_in[1];
    const float* bp   = (const float*)d_in[2];
    const float* Wih0 = (const float*)d_in[3];
    const float* Whh0 = (const float*)d_in[4];
    const float* bih0 = (const float*)d_in[5];
    const float* bhh0 = (const float*)d_in[6];
    const float* Wih1 = (const float*)d_in[7];
    const float* Whh1 = (const float*)d_in[8];
    const float* bih1 = (const float*)d_in[9];
    const float* bhh1 = (const float*)d_in[10];
    float* out = (float*)d_out;

    float* xg;
    uint16_t *Ahi, *Alo, *Wphi, *Wplo, *W0hi, *W0lo, *W1hi, *W1lo;
    int *len, *rank;
    cudaGetSymbolAddress((void**)&xg, g_xg);
    cudaGetSymbolAddress((void**)&Ahi, g_Ahi);
    cudaGetSymbolAddress((void**)&Alo, g_Alo);
    cudaGetSymbolAddress((void**)&Wphi, g_Wphi);
    cudaGetSymbolAddress((void**)&Wplo, g_Wplo);
    cudaGetSymbolAddress((void**)&W0hi, g_W0hi);
    cudaGetSymbolAddress((void**)&W0lo, g_W0lo);
    cudaGetSymbolAddress((void**)&W1hi, g_W1hi);
    cudaGetSymbolAddress((void**)&W1lo, g_W1lo);
    cudaGetSymbolAddress((void**)&len, g_len);
    cudaGetSymbolAddress((void**)&rank, g_rank);

    cudaFuncSetAttribute(gemm_mma<false, false, true>,
                         cudaFuncAttributeMaxDynamicSharedMemorySize, SMEM_DYN);
    cudaFuncSetAttribute(gemm_mma<true, true, false>,
                         cudaFuncAttributeMaxDynamicSharedMemorySize, SMEM_DYN);

    const int M = Bv * Sv;

    lengths_kernel<<<Bv, 256>>>(x, len);
    rank_kernel<<<1, Bv>>>(len, rank);
    // weight pre-conversion (tiny)
    convw<<<(Hv * Fv + 255) / 256, 256>>>(Wp, Wphi, Wplo, Hv * Fv);
    convw<<<(G3 * Hv + 255) / 256, 256>>>(Wih0, W0hi, W0lo, G3 * Hv);
    convw<<<(G3 * Hv + 255) / 256, 256>>>(Wih1, W1hi, W1lo, G3 * Hv);
    // proj = x @ Wp^T + bp -> bf16 hi/lo only
    gemm_mma<false, false, true><<<dim3(M / 128, 1), 512, SMEM_DYN>>>(
        x, nullptr, nullptr, Wphi, Wplo, bp, nullptr, Ahi, Alo, Fv, Hv);
    // xg0 = proj @ Wih0^T + bih0 (A pre-split bf16)
    gemm_mma<true, true, false><<<dim3(M / 128, 3), 512, SMEM_DYN>>>(
        nullptr, Ahi, Alo, W0hi, W0lo, bih0, xg, nullptr, nullptr, Hv, G3);
    // layer 0 recurrence: writes h1 as bf16 hi/lo into Ahi/Alo
    gru_layer_kernel<false><<<Bv, 768>>>(xg, Whh0, bhh0, len, Ahi, Alo, nullptr, nullptr);
    // xg1 = h1 @ Wih1^T + bih1
    gemm_mma<true, true, false><<<dim3(M / 128, 3), 512, SMEM_DYN>>>(
        nullptr, Ahi, Alo, W1hi, W1lo, bih1, xg, nullptr, nullptr, Hv, G3);
    // layer 1 recurrence: masked mean, scatter by rank
    gru_layer_kernel<true><<<Bv, 768>>>(xg, Whh1, bhh1, len, nullptr, nullptr, out, rank);
}

// round 15
// speedup vs baseline: 2.1710x; 2.1710x over previous
#include <cuda_runtime.h>
#include <cuda_bf16.h>
#include <cstdint>

#define Bv 128
#define Sv 1024
#define Fv 512
#define Hv 128
#define G3 (3*Hv)
#define STR 40                  // smem row stride in bf16 elems (32 data + 8 pad)
#define ARR (128*STR)           // elems per smem array (5120)
#define BUFE (4*ARR)            // elems per buffer (A_hi, A_lo, W_hi, W_lo)
#define SMEM_DYN (2*BUFE*2)     // bytes: double-buffered (81920)

typedef unsigned long long ull;

// ---------------- scratch (static device arrays; no allocation) ----------------
__device__ float    g_xg[(size_t)Bv * Sv * G3];     // xg0 / xg1
__device__ uint16_t g_Ahi[(size_t)Bv * Sv * Hv];    // bf16 hi of proj, then h1
__device__ uint16_t g_Alo[(size_t)Bv * Sv * Hv];    // bf16 lo
__device__ uint16_t g_Wphi[Hv * Fv], g_Wplo[Hv * Fv];
__device__ uint16_t g_W0hi[G3 * Hv], g_W0lo[G3 * Hv];
__device__ uint16_t g_W1hi[G3 * Hv], g_W1lo[G3 * Hv];
__device__ int      g_len[Bv];
__device__ int      g_rank[Bv];

// ---------------- f32x2 helpers ----------------
static __device__ __forceinline__ ull pk2(float x, float y) {
    ull r;
    asm("mov.b64 %0, {%1, %2};" : "=l"(r) : "f"(x), "f"(y));
    return r;
}
static __device__ __forceinline__ void fma2p(ull &d, ull a, ull b) {
    asm("fma.rn.f32x2 %0, %1, %2, %0;" : "+l"(d) : "l"(a), "l"(b));
}
static __device__ __forceinline__ float2 upk(ull v) {
    float2 f;
    asm("mov.b64 {%0, %1}, %2;" : "=f"(f.x), "=f"(f.y) : "l"(v));
    return f;
}
static __device__ __forceinline__ float fsig(float x) {
    return __fdividef(1.0f, 1.0f + __expf(-x));
}
static __device__ __forceinline__ float ftanh(float x) {
    float e = __expf(2.0f * x);
    return 1.0f - __fdividef(2.0f, e + 1.0f);
}

// ---------------- mma helpers ----------------
static __device__ __forceinline__ uint32_t smem_u32(const void* p) {
    uint32_t a;
    asm("{ .reg .u64 t; cvta.to.shared.u64 t, %1; cvt.u32.u64 %0, t; }" : "=r"(a) : "l"(p));
    return a;
}
static __device__ __forceinline__ void ldm4(uint32_t r[4], uint32_t a) {
    asm volatile("ldmatrix.sync.aligned.m8n8.x4.shared.b16 {%0,%1,%2,%3}, [%4];"
                 : "=r"(r[0]), "=r"(r[1]), "=r"(r[2]), "=r"(r[3]) : "r"(a));
}
static __device__ __forceinline__ void mma16816(float d[4], const uint32_t a[4], const uint32_t b[2]) {
    asm volatile(
        "mma.sync.aligned.m16n8k16.row.col.f32.bf16.bf16.f32 "
        "{%0,%1,%2,%3}, {%4,%5,%6,%7}, {%8,%9}, {%0,%1,%2,%3};"
        : "+f"(d[0]), "+f"(d[1]), "+f"(d[2]), "+f"(d[3])
        : "r"(a[0]), "r"(a[1]), "r"(a[2]), "r"(a[3]), "r"(b[0]), "r"(b[1]));
}
// convert 8 fp32 -> 4 bf16x2 hi words + 4 lo (residual) words, store as uint4
static __device__ __forceinline__ void cvt_store(uint16_t* dst_hi, uint16_t* dst_lo,
                                                 const float f[8]) {
    uint32_t hw[4], lw[4];
#pragma unroll
    for (int j = 0; j < 4; j++) {
        float e0 = f[2 * j], e1 = f[2 * j + 1];
        uint32_t h;
        asm("cvt.rn.bf16x2.f32 %0, %1, %2;" : "=r"(h) : "f"(e1), "f"(e0)); // lo=e0, hi=e1
        float h0 = __uint_as_float(h << 16);
        float h1 = __uint_as_float(h & 0xffff0000u);
        float l0 = e0 - h0, l1 = e1 - h1;  // exact (Sterbenz)
        uint32_t l;
        asm("cvt.rn.bf16x2.f32 %0, %1, %2;" : "=r"(l) : "f"(l1), "f"(l0));
        hw[j] = h; lw[j] = l;
    }
    *(uint4*)dst_hi = make_uint4(hw[0], hw[1], hw[2], hw[3]);
    *(uint4*)dst_lo = make_uint4(lw[0], lw[1], lw[2], lw[3]);
}

// ---------------- weight pre-conversion: fp32 -> bf16 hi/lo ----------------
__global__ void convw(const float* __restrict__ src,
                      uint16_t* __restrict__ hi, uint16_t* __restrict__ lo, int n) {
    int i = blockIdx.x * blockDim.x + threadIdx.x;
    if (i < n) {
        float v = src[i];
        __nv_bfloat16 h = __float2bfloat16(v);
        hi[i] = *(uint16_t*)&h;
        float l = v - __bfloat162float(h);
        __nv_bfloat16 hl = __float2bfloat16(l);
        lo[i] = *(uint16_t*)&hl;
    }
}

// ---------------- tensor-core GEMM: C[m,n] = A[m,:K].W[n,:K] + bias[n] ----------------
// 512 threads, 128x128 tile, K chunk 32, DOUBLE-BUFFERED dynamic smem.
// W always pre-converted bf16 hi/lo.  A either fp32 (converted in-kernel) or
// pre-converted bf16.  bf16 3-split: D = Ah.Wh + Al.Wh + Ah.Wl.
// LENGTH-AWARE: the M dimension is (b,s) with Sv=1024 rows per sequence and
// 128-row tiles that never straddle sequences; a tile whose s-range starts at
// or beyond len[b] produces values never read downstream -> early exit.
template <bool A_BF16, bool WRITE_F32, bool WRITE_BF16>
__global__ void __launch_bounds__(512, 1) gemm_mma(
    const float* __restrict__ Af,
    const uint16_t* __restrict__ Ahi, const uint16_t* __restrict__ Alo,
    const uint16_t* __restrict__ Whi, const uint16_t* __restrict__ Wlo,
    const float* __restrict__ bias,
    float* __restrict__ C, uint16_t* __restrict__ Chi, uint16_t* __restrict__ Clo,
    const int* __restrict__ len,
    int K, int N)
{
    extern __shared__ __align__(16) uint16_t sdyn[];

    const int m0 = blockIdx.x * 128, n0 = blockIdx.y * 128;

    // length-aware tile skip
    {
        const int bseq = m0 >> 10;          // m0 / Sv
        const int s0 = m0 & (Sv - 1);
        if (s0 >= len[bseq]) return;
    }

    const int tid = threadIdx.x, lane = tid & 31, wid = tid >> 5;
    const int wm = wid & 3, wn = wid >> 2;

    const int srow = tid >> 2, scg = tid & 3;
    const int selem = srow * STR + scg * 8;        // multiple of 8 -> 16B aligned

    const float*    Ag  = A_BF16 ? nullptr : (Af  + (size_t)(m0 + srow) * K + scg * 8);
    const uint16_t* Agh = A_BF16 ? (Ahi + (size_t)(m0 + srow) * K + scg * 8) : nullptr;
    const uint16_t* Agl = A_BF16 ? (Alo + (size_t)(m0 + srow) * K + scg * 8) : nullptr;
    const uint16_t* Wgh = Whi + (size_t)(n0 + srow) * K + scg * 8;
    const uint16_t* Wgl = Wlo + (size_t)(n0 + srow) * K + scg * 8;

    const uint32_t sbase = smem_u32(sdyn);

    // ldmatrix lane-address components (element offsets)
    const int a_r = lane & 15;
    const int a_c = (lane >> 4) << 3;
    const int b_r = (lane & 7) + ((lane >> 4) << 3);
    const int b_c = ((lane >> 3) & 1) << 3;

    float acc[2][4][4];
#pragma unroll
    for (int i = 0; i < 2; i++)
#pragma unroll
        for (int j = 0; j < 4; j++)
#pragma unroll
            for (int q = 0; q < 4; q++) acc[i][j][q] = 0.0f;

    const int nch = K >> 5;

    float fa[8];
    uint4 rAh, rAl, rWh, rWl;
    if (A_BF16) {
        rAh = *(const uint4*)Agh;
        rAl = *(const uint4*)Agl;
    } else {
        float4 v0 = ((const float4*)Ag)[0], v1 = ((const float4*)Ag)[1];
        fa[0]=v0.x; fa[1]=v0.y; fa[2]=v0.z; fa[3]=v0.w;
        fa[4]=v1.x; fa[5]=v1.y; fa[6]=v1.z; fa[7]=v1.w;
    }
    rWh = *(const uint4*)Wgh;
    rWl = *(const uint4*)Wgl;

    auto stage = [&](int buf) {
        uint16_t* bp = sdyn + buf * BUFE;
        if (A_BF16) {
            *(uint4*)(bp + selem)       = rAh;
            *(uint4*)(bp + ARR + selem) = rAl;
        } else {
            cvt_store(bp + selem, bp + ARR + selem, fa);
        }
        *(uint4*)(bp + 2 * ARR + selem) = rWh;
        *(uint4*)(bp + 3 * ARR + selem) = rWl;
    };

    stage(0);
    __syncthreads();

    for (int c = 0; c < nch; c++) {
        const int cur = c & 1;
        if (c + 1 < nch) {
            const int off = (c + 1) * 32;
            if (A_BF16) {
                rAh = *(const uint4*)(Agh + off);
                rAl = *(const uint4*)(Agl + off);
            } else {
                float4 v0 = ((const float4*)(Ag + off))[0], v1 = ((const float4*)(Ag + off))[1];
                fa[0]=v0.x; fa[1]=v0.y; fa[2]=v0.z; fa[3]=v0.w;
                fa[4]=v1.x; fa[5]=v1.y; fa[6]=v1.z; fa[7]=v1.w;
            }
            rWh = *(const uint4*)(Wgh + off);
            rWl = *(const uint4*)(Wgl + off);
        }

        const uint32_t base = sbase + (uint32_t)cur * (BUFE * 2u);
        const uint32_t uAh = base;
        const uint32_t uAl = base + ARR * 2u;
        const uint32_t uWh = base + 2u * ARR * 2u;
        const uint32_t uWl = base + 3u * ARR * 2u;

#pragma unroll
        for (int kb = 0; kb < 32; kb += 16) {
            uint32_t ah[2][4], al[2][4];
#pragma unroll
            for (int mf = 0; mf < 2; mf++) {
                uint32_t off = ((uint32_t)(wm * 32 + mf * 16 + a_r) * STR + kb + a_c) * 2;
                ldm4(ah[mf], uAh + off);
                ldm4(al[mf], uAl + off);
            }
            uint32_t bh[2][4], bl[2][4];
#pragma unroll
            for (int nf2 = 0; nf2 < 2; nf2++) {
                uint32_t off = ((uint32_t)(wn * 32 + nf2 * 16 + b_r) * STR + kb + b_c) * 2;
                ldm4(bh[nf2], uWh + off);
                ldm4(bl[nf2], uWl + off);
            }
#pragma unroll
            for (int mf = 0; mf < 2; mf++)
#pragma unroll
                for (int nf = 0; nf < 4; nf++) {
                    const uint32_t* bfh = &bh[nf >> 1][(nf & 1) * 2];
                    const uint32_t* bfl = &bl[nf >> 1][(nf & 1) * 2];
                    mma16816(acc[mf][nf], ah[mf], bfh);
                    mma16816(acc[mf][nf], al[mf], bfh);
                    mma16816(acc[mf][nf], ah[mf], bfl);
                }
        }
        if (c + 1 < nch) {
            stage(cur ^ 1);
            __syncthreads();
        }
    }

    // epilogue: warp covers rows [wm*32, +32), cols [wn*32, +32)
    const int erow = wm * 32 + (lane >> 2);
    const int ecol = wn * 32 + 2 * (lane & 3);
#pragma unroll
    for (int mf = 0; mf < 2; mf++) {
#pragma unroll
        for (int nf = 0; nf < 4; nf++) {
            const int r = m0 + erow + mf * 16;
            const int col = n0 + ecol + nf * 8;
            const float b0 = bias[col], b1 = bias[col + 1];
            float c0 = acc[mf][nf][0] + b0, c1 = acc[mf][nf][1] + b1;
            float c2 = acc[mf][nf][2] + b0, c3 = acc[mf][nf][3] + b1;
            if (WRITE_F32) {
                *(float2*)(C + (size_t)r * N + col) = make_float2(c0, c1);
                *(float2*)(C + (size_t)(r + 8) * N + col) = make_float2(c2, c3);
            }
            if (WRITE_BF16) {
                uint32_t H0, L0, H1, L1;
                asm("cvt.rn.bf16x2.f32 %0, %1, %2;" : "=r"(H0) : "f"(c1), "f"(c0));
                float h0 = __uint_as_float(H0 << 16);
                float h1 = __uint_as_float(H0 & 0xffff0000u);
                asm("cvt.rn.bf16x2.f32 %0, %1, %2;" : "=r"(L0) : "f"(c1 - h1), "f"(c0 - h0));
                asm("cvt.rn.bf16x2.f32 %0, %1, %2;" : "=r"(H1) : "f"(c3), "f"(c2));
                float h2 = __uint_as_float(H1 << 16);
                float h3 = __uint_as_float(H1 & 0xffff0000u);
                asm("cvt.rn.bf16x2.f32 %0, %1, %2;" : "=r"(L1) : "f"(c3 - h3), "f"(c2 - h2));
                *(uint32_t*)(Chi + (size_t)r * N + col) = H0;
                *(uint32_t*)(Clo + (size_t)r * N + col) = L0;
                *(uint32_t*)(Chi + (size_t)(r + 8) * N + col) = H1;
                *(uint32_t*)(Clo + (size_t)(r + 8) * N + col) = L1;
            }
        }
    }
}

// ---------------- lengths: count nonzero rows per batch ----------------
__global__ void lengths_kernel(const float* __restrict__ x, int* __restrict__ len) {
    const int b = blockIdx.x;
    const int warp = threadIdx.x >> 5, lane = threadIdx.x & 31;
    __shared__ int cnt;
    if (threadIdx.x == 0) cnt = 0;
    __syncthreads();
    int local = 0;
    for (int s = warp; s < Sv; s += 8) {
        const float2* row = (const float2*)(x + ((size_t)b * Sv + s) * Fv);
        float2 v = row[lane];
        bool nz = (v.x != 0.0f) || (v.y != 0.0f);
        if (__any_sync(0xffffffffu, nz)) local++;
    }
    if (lane == 0) atomicAdd(&cnt, local);
    __syncthreads();
    if (threadIdx.x == 0) len[b] = cnt;
}

// ---------------- stable-descending rank ----------------
__global__ void rank_kernel(const int* __restrict__ len, int* __restrict__ rank) {
    const int b = threadIdx.x;
    const int L = len[b];
    int r = 0;
    for (int j = 0; j < Bv; j++) {
        int Lj = len[j];
        r += (Lj > L) || (Lj == L && j < b);
    }
    rank[b] = r;
}

// ---------------- GRU recurrence (R13 / 1858us version): one CTA per sequence ----------------
// 384 threads; thread g owns Whh[g,0:128] in regs.  Sigmoids hoisted into the
// dot phase; combine by 128 threads via smem.  When !LAST, h is written as
// bf16 hi/lo (pre-split A for the next GEMM).
template <bool LAST>
__global__ void __launch_bounds__(384, 1) gru_layer_kernel(
    const float* __restrict__ xg,   // [Bv,Sv,3H]
    const float* __restrict__ Whh,  // [3H,H]
    const float* __restrict__ bhh,  // [3H]
    const int* __restrict__ len,
    uint16_t* __restrict__ h_hi,    // [Bv,Sv,H] when !LAST
    uint16_t* __restrict__ h_lo,
    float* __restrict__ out,        // [Bv,H] when LAST (sorted order)
    const int* __restrict__ rank)
{
    const int b = blockIdx.x;
    const int g = threadIdx.x;

    __shared__ __align__(16) float h_sh[Hv];
    __shared__ float r_sh[Hv];
    __shared__ float omz_sh[Hv];   // 1 - z
    __shared__ float zh_sh[Hv];    // z * h_prev
    __shared__ float hn_sh[Hv];
    __shared__ float xn_sh[Hv];

    ull w[64];
    {
        const float4* wp = (const float4*)(Whh + (size_t)g * Hv);
#pragma unroll
        for (int i = 0; i < 32; i++) {
            float4 v = wp[i];
            w[2 * i]     = pk2(v.x, v.y);
            w[2 * i + 1] = pk2(v.z, v.w);
        }
    }
    const float bh = bhh[g];
    const int L = len[b];
    const float* xb = xg + (size_t)b * Sv * G3 + g;
    const int gate = g >> 7;        // 0 = r, 1 = z, 2 = n
    const int j = g & (Hv - 1);

    if (g < Hv) h_sh[g] = 0.0f;
    float x0 = (L > 0) ? xb[0] : 0.0f;
    float x1 = (L > 1) ? xb[G3] : 0.0f;
    __syncthreads();

    float oacc = 0.0f;

    for (int s = 0; s < L; s++) {
        float xN = (s + 2 < L) ? xb[(size_t)(s + 2) * G3] : 0.0f;

        // dot: hg = bias_eff + h . Whh[g,:]   (x folded for r/z gates)
        ull a0 = pk2((gate == 2) ? bh : (bh + x0), 0.0f);
        ull a1 = 0ull;
        const ulonglong2* hp = (const ulonglong2*)h_sh;
#pragma unroll
        for (int i = 0; i < 32; i++) {
            ulonglong2 hv = hp[i];
            fma2p(a0, w[2 * i],     hv.x);
            fma2p(a1, w[2 * i + 1], hv.y);
        }
        float2 f0 = upk(a0), f1 = upk(a1);
        const float hg = (f0.x + f1.x) + (f0.y + f1.y);

        if (gate == 0) {
            r_sh[j] = fsig(hg);
        } else if (gate == 1) {
            float z = fsig(hg);
            omz_sh[j] = 1.0f - z;
            zh_sh[j] = z * h_sh[j];
        } else {
            hn_sh[j] = hg;
            xn_sh[j] = x0;
        }
        __syncthreads();

        if (g < Hv) {
            float n = ftanh(fmaf(r_sh[g], hn_sh[g], xn_sh[g]));
            float hnew = fmaf(n, omz_sh[g], zh_sh[g]);
            h_sh[g] = hnew;
            if (!LAST) {
                size_t idx = ((size_t)b * Sv + s) * Hv + g;
                __nv_bfloat16 hh = __float2bfloat16(hnew);
                h_hi[idx] = *(uint16_t*)&hh;
                float rem = hnew - __bfloat162float(hh);
                __nv_bfloat16 hl = __float2bfloat16(rem);
                h_lo[idx] = *(uint16_t*)&hl;
            } else {
                oacc += hnew;
            }
        }
        __syncthreads();
        x0 = x1;
        x1 = xN;
    }

    if (LAST && g < Hv) {
        out[(size_t)rank[b] * Hv + g] = oacc * (1.0f / (float)Sv);
    }
}

// ---------------- launch ----------------
extern "C" void kernel_launch(void* const* d_in, const int* in_sizes, int n_in,
                              void* d_out, int out_size) {
    (void)in_sizes; (void)n_in; (void)out_size;
    const float* x    = (const float*)d_in[0];
    const float* Wp   = (const float*)d_in[1];
    const float* bp   = (const float*)d_in[2];
    const float* Wih0 = (const float*)d_in[3];
    const float* Whh0 = (const float*)d_in[4];
    const float* bih0 = (const float*)d_in[5];
    const float* bhh0 = (const float*)d_in[6];
    const float* Wih1 = (const float*)d_in[7];
    const float* Whh1 = (const float*)d_in[8];
    const float* bih1 = (const float*)d_in[9];
    const float* bhh1 = (const float*)d_in[10];
    float* out = (float*)d_out;

    float* xg;
    uint16_t *Ahi, *Alo, *Wphi, *Wplo, *W0hi, *W0lo, *W1hi, *W1lo;
    int *len, *rank;
    cudaGetSymbolAddress((void**)&xg, g_xg);
    cudaGetSymbolAddress((void**)&Ahi, g_Ahi);
    cudaGetSymbolAddress((void**)&Alo, g_Alo);
    cudaGetSymbolAddress((void**)&Wphi, g_Wphi);
    cudaGetSymbolAddress((void**)&Wplo, g_Wplo);
    cudaGetSymbolAddress((void**)&W0hi, g_W0hi);
    cudaGetSymbolAddress((void**)&W0lo, g_W0lo);
    cudaGetSymbolAddress((void**)&W1hi, g_W1hi);
    cudaGetSymbolAddress((void**)&W1lo, g_W1lo);
    cudaGetSymbolAddress((void**)&len, g_len);
    cudaGetSymbolAddress((void**)&rank, g_rank);

    cudaFuncSetAttribute(gemm_mma<false, false, true>,
                         cudaFuncAttributeMaxDynamicSharedMemorySize, SMEM_DYN);
    cudaFuncSetAttribute(gemm_mma<true, true, false>,
                         cudaFuncAttributeMaxDynamicSharedMemorySize, SMEM_DYN);

    const int M = Bv * Sv;

    lengths_kernel<<<Bv, 256>>>(x, len);
    rank_kernel<<<1, Bv>>>(len, rank);
    // weight pre-conversion (tiny)
    convw<<<(Hv * Fv + 255) / 256, 256>>>(Wp, Wphi, Wplo, Hv * Fv);
    convw<<<(G3 * Hv + 255) / 256, 256>>>(Wih0, W0hi, W0lo, G3 * Hv);
    convw<<<(G3 * Hv + 255) / 256, 256>>>(Wih1, W1hi, W1lo, G3 * Hv);
    // proj = x @ Wp^T + bp -> bf16 hi/lo only (length-aware tiles)
    gemm_mma<false, false, true><<<dim3(M / 128, 1), 512, SMEM_DYN>>>(
        x, nullptr, nullptr, Wphi, Wplo, bp, nullptr, Ahi, Alo, len, Fv, Hv);
    // xg0 = proj @ Wih0^T + bih0 (A pre-split bf16, length-aware)
    gemm_mma<true, true, false><<<dim3(M / 128, 3), 512, SMEM_DYN>>>(
        nullptr, Ahi, Alo, W0hi, W0lo, bih0, xg, nullptr, nullptr, len, Hv, G3);
    // layer 0 recurrence: writes h1 as bf16 hi/lo into Ahi/Alo
    gru_layer_kernel<false><<<Bv, 384>>>(xg, Whh0, bhh0, len, Ahi, Alo, nullptr, nullptr);
    // xg1 = h1 @ Wih1^T + bih1 (length-aware)
    gemm_mma<true, true, false><<<dim3(M / 128, 3), 512, SMEM_DYN>>>(
        nullptr, Ahi, Alo, W1hi, W1lo, bih1, xg, nullptr, nullptr, len, Hv, G3);
    // layer 1 recurrence: masked mean, scatter by rank
    gru_layer_kernel<true><<<Bv, 384>>>(xg, Whh1, bhh1, len, nullptr, nullptr, out, rank);
}